// round 16
// baseline (speedup 1.0000x reference)
#include <cuda_runtime.h>
#include <cuda_bf16.h>
#include <math.h>
#include <mma.h>
#include <cstdint>

using namespace nvcuda;

#define B_SZ 2
#define S_LEN 2048
#define D_DIM 2048
#define NH 16
#define HD 128
#define HALF_H 8
#define EPS_RMS 1e-6f
#define EPS_HN 1e-5f
// 1/sqrt(128) * log2(e): folded into Q so QK^T scores are log2-domain
#define QSCALE 0.12751743f

// ---------------- scratch (no allocations allowed) ----------------
__device__ float g_xn[B_SZ * S_LEN * D_DIM];
__device__ float g_q [B_SZ * S_LEN * D_DIM];
__device__ float g_k [B_SZ * S_LEN * D_DIM];
__device__ float g_v [B_SZ * S_LEN * D_DIM];
__device__ float g_attn[B_SZ * S_LEN * D_DIM];
__device__ float g_ctx [B_SZ * S_LEN * (D_DIM / 2)];   // y only: [4096][1024]
__device__ float g_wr  [4 * D_DIM * D_DIM];   // 0-2: wq,wk,wv rounded; 3: wo2 [1024][2048]
__device__ float g_bias2[D_DIM];
__device__ float g_bias_part[16 * D_DIM];
__device__ float g_rope[2 * S_LEN * 64];      // cos | sin tables
__device__ float g_lam[HALF_H];

// ---------------- helpers ----------------
__device__ __forceinline__ uint32_t smem_u32(const void* p) {
    uint32_t a;
    asm("{ .reg .u64 t; cvta.to.shared.u64 t, %1; cvt.u32.u64 %0, t; }" : "=r"(a) : "l"(p));
    return a;
}
__device__ __forceinline__ void cp_async16(uint32_t dst, const void* src) {
    asm volatile("cp.async.cg.shared.global [%0], [%1], 16;" :: "r"(dst), "l"(src));
}
__device__ __forceinline__ void cp_commit() {
    asm volatile("cp.async.commit_group;");
}
template<int N> __device__ __forceinline__ void cp_wait() {
    asm volatile("cp.async.wait_group %0;" :: "n"(N));
}

// ---------------- tf32 rounding of wq,wk,wv ----------------
__global__ __launch_bounds__(256) void round_w_kernel(const float* __restrict__ w0,
                                                      const float* __restrict__ w1,
                                                      const float* __restrict__ w2,
                                                      float* __restrict__ dst) {
    const int z = blockIdx.y;
    const float* src = (z == 0) ? w0 : (z == 1) ? w1 : w2;
    float* d = dst + (size_t)z * D_DIM * D_DIM;
    int i4 = blockIdx.x * 256 + threadIdx.x;
    float4 v = *(const float4*)(src + (size_t)i4 * 4);
    v.x = wmma::__float_to_tf32(v.x); v.y = wmma::__float_to_tf32(v.y);
    v.z = wmma::__float_to_tf32(v.z); v.w = wmma::__float_to_tf32(v.w);
    *(float4*)(d + (size_t)i4 * 4) = v;
}

// ---------------- fold wo ----------------
__global__ __launch_bounds__(256) void wo_fold_kernel(const float* __restrict__ wo,
                                                      const float* __restrict__ gamma,
                                                      float* __restrict__ dst) {
    int i4 = blockIdx.x * 256 + threadIdx.x;      // over 1024*512 float4
    int row = i4 >> 9;                            // 0..1023
    int c4 = i4 & 511;
    int h = row >> 7;
    float g1 = gamma[h], g2 = gamma[h + 8];
    float4 a = *(const float4*)(wo + (size_t)row * D_DIM + c4 * 4);
    float4 b = *(const float4*)(wo + (size_t)(row + 1024) * D_DIM + c4 * 4);
    float4 v;
    v.x = wmma::__float_to_tf32(g1 * a.x + g2 * b.x);
    v.y = wmma::__float_to_tf32(g1 * a.y + g2 * b.y);
    v.z = wmma::__float_to_tf32(g1 * a.z + g2 * b.z);
    v.w = wmma::__float_to_tf32(g1 * a.w + g2 * b.w);
    *(float4*)(dst + (size_t)row * D_DIM + c4 * 4) = v;
}

// ---------------- bias2 = bo + beta_vec @ wo : two-stage reduction ----------------
__global__ __launch_bounds__(256) void bias2_stage1(const float* __restrict__ wo,
                                                    const float* __restrict__ beta) {
    const int nb = blockIdx.x, db = blockIdx.y;
    const int nl = threadIdx.x & 127;
    const int dhalf = threadIdx.x >> 7;
    const int n = nb * 128 + nl;
    float s = 0.f;
#pragma unroll 4
    for (int i = 0; i < 64; i++) {
        int d = db * 128 + dhalf * 64 + i;
        s = fmaf(beta[d >> 7], wo[(size_t)d * D_DIM + n], s);
    }
    __shared__ float sh[256];
    sh[threadIdx.x] = s;
    __syncthreads();
    if (dhalf == 0)
        g_bias_part[db * D_DIM + n] = s + sh[threadIdx.x + 128];
}
__global__ __launch_bounds__(256) void bias2_stage2(const float* __restrict__ bo) {
    int n = blockIdx.x * 256 + threadIdx.x;
    float s = bo[n];
#pragma unroll
    for (int i = 0; i < 16; i++) s += g_bias_part[i * D_DIM + n];
    g_bias2[n] = s;
}

// ---------------- RMSNorm, float4 (emits tf32-rounded output) ----------------
__global__ __launch_bounds__(256) void rmsnorm_kernel(const float* __restrict__ x,
                                                      const float* __restrict__ g,
                                                      float* __restrict__ out) {
    int row = blockIdx.x;
    const float* xr = x + (size_t)row * D_DIM;
    float* orow = out + (size_t)row * D_DIM;
    float4 xv[2];
    float s = 0.f;
#pragma unroll
    for (int it = 0; it < 2; it++) {
        xv[it] = *(const float4*)(xr + (threadIdx.x + it * 256) * 4);
        float a0 = xv[it].x + 2.f * EPS_RMS, a1 = xv[it].y + 2.f * EPS_RMS;
        float a2 = xv[it].z + 2.f * EPS_RMS, a3 = xv[it].w + 2.f * EPS_RMS;
        s = fmaf(a0, a0, s); s = fmaf(a1, a1, s);
        s = fmaf(a2, a2, s); s = fmaf(a3, a3, s);
    }
#pragma unroll
    for (int off = 16; off; off >>= 1) s += __shfl_xor_sync(0xffffffffu, s, off);
    __shared__ float red[8];
    __shared__ float sinv;
    if ((threadIdx.x & 31) == 0) red[threadIdx.x >> 5] = s;
    __syncthreads();
    if (threadIdx.x == 0) {
        float t = 0.f;
#pragma unroll
        for (int i = 0; i < 8; i++) t += red[i];
        float n = sqrtf(t) * 45.254833995939045f;  // sqrt(2048)
        sinv = 1.0f / (n + EPS_RMS);
    }
    __syncthreads();
    float inv = sinv;
#pragma unroll
    for (int it = 0; it < 2; it++) {
        int d = (threadIdx.x + it * 256) * 4;
        float4 gv = *(const float4*)(g + d);
        float4 o;
        o.x = wmma::__float_to_tf32((xv[it].x + EPS_RMS) * inv * gv.x);
        o.y = wmma::__float_to_tf32((xv[it].y + EPS_RMS) * inv * gv.y);
        o.z = wmma::__float_to_tf32((xv[it].z + EPS_RMS) * inv * gv.z);
        o.w = wmma::__float_to_tf32((xv[it].w + EPS_RMS) * inv * gv.w);
        *(float4*)(orow + d) = o;
    }
}

// ---------------- TF32 WMMA GEMM, cp.async 2-stage GBK=64, fused RoPE epilogue ----------------
#define CTA_M 128
#define CTA_N 256
#define GBK 64
#define LDA 68
#define LDB 260
#define LDC 132
#define STAGE_A (CTA_M * LDA)            // 8704 floats
#define STAGE_B (GBK * LDB)              // 16640 floats
#define STAGE_FL (STAGE_A + STAGE_B)     // 25344 floats
#define NSTAGE 2
#define GEMM_SMEM (NSTAGE * STAGE_FL * 4)   // 202752 B

__global__ __launch_bounds__(256) void gemm_tf32(const float* __restrict__ A,
                                                 const float* __restrict__ Wbase,
                                                 int zoff, int Kdim, int roundOut, int doRope,
                                                 const float* __restrict__ b0,
                                                 const float* __restrict__ b1,
                                                 const float* __restrict__ b2,
                                                 float* __restrict__ C0,
                                                 float* __restrict__ C1,
                                                 float* __restrict__ C2) {
    extern __shared__ float sm[];
    const uint32_t smem_base = smem_u32(sm);
    const int z = blockIdx.z;
    const float* W    = Wbase + (size_t)(z + zoff) * D_DIM * D_DIM;
    const float* bias = (z == 0) ? b0 : (z == 1) ? b1 : b2;
    float* C          = (z == 0) ? C0 : (z == 1) ? C1 : C2;

    const int tid = threadIdx.x;
    const int warpId = tid >> 5;
    const int wy = warpId >> 2;
    const int wx = warpId & 3;
    const int mBase = blockIdx.y * CTA_M;
    const int nBase = blockIdx.x * CTA_N;
    const int nkt = Kdim / GBK;
    const bool rope = doRope && (z <= 1);
    const float qs = (z == 0) ? QSCALE : 1.0f;

    wmma::fragment<wmma::accumulator, 16, 16, 8, float> acc[4][4];
#pragma unroll
    for (int i = 0; i < 4; i++)
#pragma unroll
        for (int j = 0; j < 4; j++) wmma::fill_fragment(acc[i][j], 0.0f);

    auto stage = [&](int buf, int k0) {
        uint32_t sa = smem_base + (uint32_t)(buf * STAGE_FL * 4);
        uint32_t sb = sa + STAGE_A * 4;
        // A tile: 128 rows x 16 f4-chunks = 2048
#pragma unroll
        for (int it = 0; it < 8; it++) {
            int idx = tid + it * 256;
            int row = idx >> 4, c = idx & 15;
            cp_async16(sa + (uint32_t)(row * LDA + c * 4) * 4,
                       A + (size_t)(mBase + row) * Kdim + k0 + c * 4);
        }
        // B tile: 64 rows x 64 f4-chunks = 4096
#pragma unroll
        for (int it = 0; it < 16; it++) {
            int idx = tid + it * 256;
            int row = idx >> 6, c = idx & 63;
            cp_async16(sb + (uint32_t)(row * LDB + c * 4) * 4,
                       W + (size_t)(k0 + row) * D_DIM + nBase + c * 4);
        }
    };

    stage(0, 0);
    cp_commit();

    for (int t = 0; t < nkt; t++) {
        cp_wait<0>();
        __syncthreads();
        if (t + 1 < nkt) { stage((t + 1) & 1, (t + 1) * GBK); cp_commit(); }

        const float* As = sm + (t & 1) * STAGE_FL;
        const float* Bs = As + STAGE_A;
#pragma unroll
        for (int kk = 0; kk < GBK; kk += 8) {
            wmma::fragment<wmma::matrix_a, 16, 16, 8, wmma::precision::tf32, wmma::row_major> af[4];
            wmma::fragment<wmma::matrix_b, 16, 16, 8, wmma::precision::tf32, wmma::row_major> bf[4];
#pragma unroll
            for (int i = 0; i < 4; i++)
                wmma::load_matrix_sync(af[i], &As[(wy * 64 + i * 16) * LDA + kk], LDA);
#pragma unroll
            for (int j = 0; j < 4; j++)
                wmma::load_matrix_sync(bf[j], &Bs[kk * LDB + wx * 64 + j * 16], LDB);
#pragma unroll
            for (int i = 0; i < 4; i++)
#pragma unroll
                for (int j = 0; j < 4; j++)
                    wmma::mma_sync(acc[i][j], af[i], bf[j], acc[i][j]);
        }
    }
    __syncthreads();

    float* Cs = sm;
#pragma unroll
    for (int half = 0; half < 2; half++) {
        if ((wx >> 1) == half) {
#pragma unroll
            for (int i = 0; i < 4; i++)
#pragma unroll
                for (int j = 0; j < 4; j++)
                    wmma::store_matrix_sync(&Cs[(wy * 64 + i * 16) * LDC + (wx & 1) * 64 + j * 16],
                                            acc[i][j], LDC, wmma::mem_row_major);
        }
        __syncthreads();
        if (rope) {
#pragma unroll
            for (int it = 0; it < 8; it++) {
                int idx = tid + it * 256;          // 2048 = 128 rows x 16 f4 (cols 0..63)
                int row = idx >> 4, c4 = idx & 15;
                int j = c4 * 4;
                float4 a = *(float4*)&Cs[row * LDC + j];
                float4 b = *(float4*)&Cs[row * LDC + j + 64];
                int col = nBase + half * 128 + j;
                float4 bi  = *(const float4*)(bias + col);
                float4 bi2 = *(const float4*)(bias + col + 64);
                a.x = (a.x + bi.x) * qs;  a.y = (a.y + bi.y) * qs;
                a.z = (a.z + bi.z) * qs;  a.w = (a.w + bi.w) * qs;
                b.x = (b.x + bi2.x) * qs; b.y = (b.y + bi2.y) * qs;
                b.z = (b.z + bi2.z) * qs; b.w = (b.w + bi2.w) * qs;
                int s = (mBase + row) & (S_LEN - 1);
                float4 co = *(const float4*)&g_rope[s * 64 + j];
                float4 si = *(const float4*)&g_rope[S_LEN * 64 + s * 64 + j];
                float4 lo, hi;
                lo.x = wmma::__float_to_tf32(a.x * co.x - b.x * si.x);
                lo.y = wmma::__float_to_tf32(a.y * co.y - b.y * si.y);
                lo.z = wmma::__float_to_tf32(a.z * co.z - b.z * si.z);
                lo.w = wmma::__float_to_tf32(a.w * co.w - b.w * si.w);
                hi.x = wmma::__float_to_tf32(b.x * co.x + a.x * si.x);
                hi.y = wmma::__float_to_tf32(b.y * co.y + a.y * si.y);
                hi.z = wmma::__float_to_tf32(b.z * co.z + a.z * si.z);
                hi.w = wmma::__float_to_tf32(b.w * co.w + a.w * si.w);
                float* Crow = C + (size_t)(mBase + row) * D_DIM + col;
                *(float4*)Crow = lo;
                *(float4*)(Crow + 64) = hi;
            }
        } else {
#pragma unroll
            for (int it = 0; it < 16; it++) {
                int idx = tid + it * 256;
                int row = idx >> 5, c = idx & 31;
                float4 v = *(float4*)&Cs[row * LDC + c * 4];
                int col = nBase + half * 128 + c * 4;
                float4 bi = *(const float4*)(bias + col);
                v.x += bi.x; v.y += bi.y; v.z += bi.z; v.w += bi.w;
                if (roundOut) {
                    v.x = wmma::__float_to_tf32(v.x); v.y = wmma::__float_to_tf32(v.y);
                    v.z = wmma::__float_to_tf32(v.z); v.w = wmma::__float_to_tf32(v.w);
                }
                *(float4*)(C + (size_t)(mBase + row) * D_DIM + col) = v;
            }
        }
        __syncthreads();
    }
}

// ---------------- RoPE table (fp64, once) ----------------
__global__ __launch_bounds__(256) void rope_table_kernel(const int* __restrict__ positions) {
    int idx = blockIdx.x * 256 + threadIdx.x;      // S_LEN*64
    int j = idx & 63;
    int s = idx >> 6;
    double e = (double)(2 * j) * (1.0 / 128.0);
    double invf = exp(-e * 13.122363377404328);    // ln(500000)
    double f = (double)positions[s] * invf;
    g_rope[idx] = (float)cos(f);
    g_rope[S_LEN * 64 + idx] = (float)sin(f);
}

// ---------------- lambda per head ----------------
__global__ __launch_bounds__(256) void lam_kernel(const float* __restrict__ lq1,
                                                  const float* __restrict__ lk1,
                                                  const float* __restrict__ lq2,
                                                  const float* __restrict__ lk2,
                                                  const float* __restrict__ lam_init) {
    int h = threadIdx.x >> 5;
    int lane = threadIdx.x & 31;
    float s1 = 0.f, s2 = 0.f;
#pragma unroll
    for (int d = lane; d < HD; d += 32) {
        s1 = fmaf(lq1[h * HD + d], lk1[h * HD + d], s1);
        s2 = fmaf(lq2[h * HD + d], lk2[h * HD + d], s2);
    }
#pragma unroll
    for (int off = 16; off; off >>= 1) {
        s1 += __shfl_xor_sync(0xffffffffu, s1, off);
        s2 += __shfl_xor_sync(0xffffffffu, s2, off);
    }
    if (lane == 0 && h < HALF_H) {
        float l = expf(s1) - expf(s2) + lam_init[h];
        g_lam[h] = fminf(fmaxf(l, 0.f), 1.f);
    }
}

// ---------------- WMMA flash attention v4: log2 softmax, graded cp.async waits ----------------
#define FM 128
#define FN 64
#define FLDQ 132
#define FLDP 72
#define KV_FL (64 * FLDQ)
#define F_QS 0
#define F_PS (FM * FLDQ)
#define F_B0 (F_PS + FM * FLDP)
#define F_ROW (F_B0 + 3 * KV_FL)
#define F_MI (F_ROW + 256)
#define F_LI (F_MI + FM)
#define F_AL (F_LI + FM)
#define FLASH_SMEM ((F_AL + FM) * 4)      // 208384 B

__global__ __launch_bounds__(256) void flash_wmma(const float* __restrict__ Q,
                                                  const float* __restrict__ K,
                                                  const float* __restrict__ V,
                                                  float* __restrict__ O) {
    extern __shared__ float sm[];
    const uint32_t smem_base = smem_u32(sm);
    float* Qs = sm + F_QS;
    float* Ps = sm + F_PS;
    float* rowtile = sm + F_ROW;
    float* mi = sm + F_MI;
    float* li = sm + F_LI;
    float* al = sm + F_AL;

    const int qBase = (gridDim.x - 1 - blockIdx.x) * FM;   // heavy blocks first
    const int h = blockIdx.y;
    const int b = blockIdx.z;
    const int tid = threadIdx.x;
    const int warp = tid >> 5;
    const int wy = warp >> 1;
    const int wx = warp & 1;
    const size_t headOff = (size_t)h * HD;
    const int nIter = qBase / FN + 2;

    auto stageTile = [&](int fOff, const float* src, int n0) {
#pragma unroll
        for (int it = 0; it < 8; it++) {
            int idx = tid + it * 256;
            int row = idx >> 5, c4 = idx & 31;
            cp_async16(smem_base + (uint32_t)(fOff + row * FLDQ + c4 * 4) * 4,
                       src + ((size_t)(b * S_LEN + n0 + row)) * D_DIM + headOff + c4 * 4);
        }
    };

#pragma unroll
    for (int it = 0; it < 16; it++) {
        int idx = tid + it * 256;
        int row = idx >> 5, c4 = idx & 31;
        cp_async16(smem_base + (uint32_t)(F_QS + row * FLDQ + c4 * 4) * 4,
                   Q + ((size_t)(b * S_LEN + qBase + row)) * D_DIM + headOff + c4 * 4);
    }
    stageTile(F_B0, K, 0);
    stageTile(F_B0 + KV_FL, V, 0);
    cp_commit();

    rowtile[tid] = (float)(tid >> 4);
    if (tid < FM) { mi[tid] = -1e30f; li[tid] = 0.f; }
    cp_wait<0>();
    __syncthreads();

    wmma::fragment<wmma::accumulator, 16, 16, 8, float> rf;
    wmma::load_matrix_sync(rf, rowtile, 16, wmma::mem_row_major);

    wmma::fragment<wmma::accumulator, 16, 16, 8, float> oacc[2][4];
#pragma unroll
    for (int i = 0; i < 2; i++)
#pragma unroll
        for (int j = 0; j < 4; j++) wmma::fill_fragment(oacc[i][j], 0.f);

    for (int t = 0; t < nIter; t++) {
        const int kb = (3 - (t % 3)) % 3;
        const int vb = (kb + 1) % 3;
        const int fb = 3 - kb - vb;
        float* Ks = sm + F_B0 + kb * KV_FL;
        float* Vs = sm + F_B0 + vb * KV_FL;
        const int n0 = t * FN;
        const bool more = (t + 1 < nIter);

        if (more) { stageTile(F_B0 + fb * KV_FL, K, n0 + FN); cp_commit(); }

        // ---- S = Q @ K^T (Q pre-scaled: log2-domain scores)
        {
            const int sx = warp & 1;
            wmma::fragment<wmma::accumulator, 16, 16, 8, float> sacc[2][2];
#pragma unroll
            for (int i = 0; i < 2; i++)
#pragma unroll
                for (int j = 0; j < 2; j++) wmma::fill_fragment(sacc[i][j], 0.f);
#pragma unroll
            for (int k = 0; k < HD; k += 8) {
                wmma::fragment<wmma::matrix_a, 16, 16, 8, wmma::precision::tf32, wmma::row_major> af[2];
                wmma::fragment<wmma::matrix_b, 16, 16, 8, wmma::precision::tf32, wmma::col_major> bf[2];
#pragma unroll
                for (int i = 0; i < 2; i++)
                    wmma::load_matrix_sync(af[i], &Qs[(wy * 32 + i * 16) * FLDQ + k], FLDQ);
#pragma unroll
                for (int j = 0; j < 2; j++)
                    wmma::load_matrix_sync(bf[j], &Ks[(sx * 32 + j * 16) * FLDQ + k], FLDQ);
#pragma unroll
                for (int i = 0; i < 2; i++)
#pragma unroll
                    for (int j = 0; j < 2; j++)
                        wmma::mma_sync(sacc[i][j], af[i], bf[j], sacc[i][j]);
            }
#pragma unroll
            for (int i = 0; i < 2; i++)
#pragma unroll
                for (int j = 0; j < 2; j++)
                    wmma::store_matrix_sync(&Ps[(wy * 32 + i * 16) * FLDP + sx * 32 + j * 16],
                                            sacc[i][j], FLDP, wmma::mem_row_major);
        }
        __syncthreads();

        if (more) { stageTile(F_B0 + kb * KV_FL, V, n0 + FN); cp_commit(); }

        // ---- online softmax (log2 domain): registers, masked only on last 2 tiles
        {
            int r = tid >> 1;
            int part = tid & 1;
            float* Prow = Ps + r * FLDP + part * 32;
            float v[32];
            float lm = -1e30f;
            if (t >= nIter - 2) {
                int cbase = n0 + part * 32 - qBase - r;
#pragma unroll
                for (int n = 0; n < 32; n++) {
                    float x = Prow[n];
                    if (cbase + n > 0) x = -1e30f;
                    v[n] = x;
                    lm = fmaxf(lm, x);
                }
            } else {
#pragma unroll
                for (int n = 0; n < 32; n++) {
                    v[n] = Prow[n];
                    lm = fmaxf(lm, v[n]);
                }
            }
            lm = fmaxf(lm, __shfl_xor_sync(0xffffffffu, lm, 1));
            float oldm = mi[r];
            float newm = fmaxf(oldm, lm);
            float lsum = 0.f;
#pragma unroll
            for (int n = 0; n < 32; n++) {
                float e = exp2f(v[n] - newm);
                Prow[n] = wmma::__float_to_tf32(e);
                lsum += e;
            }
            lsum += __shfl_xor_sync(0xffffffffu, lsum, 1);
            if (part == 0) {
                float alpha = exp2f(oldm - newm);
                mi[r] = newm;
                li[r] = li[r] * alpha + lsum;
                al[r] = alpha;
            }
        }
        // graded wait: retire V(t) only; K(t+1)/V(t+1) may remain in flight
        if (more) cp_wait<2>(); else cp_wait<0>();
        __syncthreads();

        // ---- rescale O accumulators (rowid trick)
#pragma unroll
        for (int e = 0; e < 8; e++) {
            int rl = (int)rf.x[e];
            float a0 = al[wy * 32 + rl];
            float a1 = al[wy * 32 + 16 + rl];
#pragma unroll
            for (int j = 0; j < 4; j++) {
                oacc[0][j].x[e] *= a0;
                oacc[1][j].x[e] *= a1;
            }
        }

        // ---- O += P @ V
#pragma unroll
        for (int k = 0; k < FN; k += 8) {
            wmma::fragment<wmma::matrix_a, 16, 16, 8, wmma::precision::tf32, wmma::row_major> af[2];
            wmma::fragment<wmma::matrix_b, 16, 16, 8, wmma::precision::tf32, wmma::row_major> bf[4];
#pragma unroll
            for (int i = 0; i < 2; i++)
                wmma::load_matrix_sync(af[i], &Ps[(wy * 32 + i * 16) * FLDP + k], FLDP);
#pragma unroll
            for (int j = 0; j < 4; j++)
                wmma::load_matrix_sync(bf[j], &Vs[k * FLDQ + wx * 64 + j * 16], FLDQ);
#pragma unroll
            for (int i = 0; i < 2; i++)
#pragma unroll
                for (int j = 0; j < 4; j++)
                    wmma::mma_sync(oacc[i][j], af[i], bf[j], oacc[i][j]);
        }

        // retire K(t+1) before next S-phase; V(t+1) stays outstanding
        if (more) cp_wait<1>();
        __syncthreads();
    }

    // epilogue: normalize in registers, store fragments directly to global
#pragma unroll
    for (int e = 0; e < 8; e++) {
        int rl = (int)rf.x[e];
        float i0 = 1.0f / li[wy * 32 + rl];
        float i1 = 1.0f / li[wy * 32 + 16 + rl];
#pragma unroll
        for (int j = 0; j < 4; j++) {
            oacc[0][j].x[e] *= i0;
            oacc[1][j].x[e] *= i1;
        }
    }
#pragma unroll
    for (int i = 0; i < 2; i++)
#pragma unroll
        for (int j = 0; j < 4; j++)
            wmma::store_matrix_sync(
                O + ((size_t)(b * S_LEN + qBase + wy * 32 + i * 16)) * D_DIM + headOff + wx * 64 + j * 16,
                oacc[i][j], D_DIM, wmma::mem_row_major);
}

// ---------------- diff combine + headwise LayerNorm (warp per row x head, float4) ----------------
__global__ __launch_bounds__(256) void combine_kernel(const float* __restrict__ attn,
                                                      float* __restrict__ ctx) {
    int row = blockIdx.x;                 // 0..4095
    int h = threadIdx.x >> 5;             // 0..7
    int lane = threadIdx.x & 31;
    size_t base = (size_t)row * D_DIM;
    float lam = g_lam[h];

    float4 a1 = *(const float4*)(attn + base + h * HD + lane * 4);
    float4 a2 = *(const float4*)(attn + base + (h + 8) * HD + lane * 4);
    float4 o;
    o.x = a1.x - lam * a2.x; o.y = a1.y - lam * a2.y;
    o.z = a1.z - lam * a2.z; o.w = a1.w - lam * a2.w;

    float s = o.x + o.y + o.z + o.w;
#pragma unroll
    for (int off = 16; off; off >>= 1) s += __shfl_xor_sync(0xffffffffu, s, off);
    float mean = s * (1.0f / 128.0f);

    float dx = o.x - mean, dy = o.y - mean, dz = o.z - mean, dw = o.w - mean;
    float s2 = dx * dx + dy * dy + dz * dz + dw * dw;
#pragma unroll
    for (int off = 16; off; off >>= 1) s2 += __shfl_xor_sync(0xffffffffu, s2, off);
    float inv = rsqrtf(s2 * (1.0f / 128.0f) + EPS_HN);

    float4 y;
    y.x = wmma::__float_to_tf32(dx * inv);
    y.y = wmma::__float_to_tf32(dy * inv);
    y.z = wmma::__float_to_tf32(dz * inv);
    y.w = wmma::__float_to_tf32(dw * inv);
    *(float4*)(ctx + (size_t)row * (D_DIM / 2) + h * HD + lane * 4) = y;
}

// ---------------- launch ----------------
extern "C" void kernel_launch(void* const* d_in, const int* in_sizes, int n_in,
                              void* d_out, int out_size) {
    const float* x         = (const float*)d_in[0];
    const int*   positions = (const int*)  d_in[1];
    const float* wq        = (const float*)d_in[2];
    const float* bq        = (const float*)d_in[3];
    const float* wk        = (const float*)d_in[4];
    const float* bk        = (const float*)d_in[5];
    const float* wv        = (const float*)d_in[6];
    const float* bv        = (const float*)d_in[7];
    const float* wo        = (const float*)d_in[8];
    const float* bo        = (const float*)d_in[9];
    const float* g         = (const float*)d_in[10];
    const float* gamma     = (const float*)d_in[11];
    const float* beta      = (const float*)d_in[12];
    const float* lam_init  = (const float*)d_in[13];
    const float* lq1       = (const float*)d_in[14];
    const float* lk1       = (const float*)d_in[15];
    const float* lq2       = (const float*)d_in[16];
    const float* lk2       = (const float*)d_in[17];
    float* out = (float*)d_out;

    float *p_xn, *p_q, *p_k, *p_v, *p_attn, *p_ctx, *p_wr, *p_bias2;
    cudaGetSymbolAddress((void**)&p_xn,   g_xn);
    cudaGetSymbolAddress((void**)&p_q,    g_q);
    cudaGetSymbolAddress((void**)&p_k,    g_k);
    cudaGetSymbolAddress((void**)&p_v,    g_v);
    cudaGetSymbolAddress((void**)&p_attn, g_attn);
    cudaGetSymbolAddress((void**)&p_ctx,  g_ctx);
    cudaGetSymbolAddress((void**)&p_wr,   g_wr);
    cudaGetSymbolAddress((void**)&p_bias2, g_bias2);

    const int M = B_SZ * S_LEN;   // 4096

    dim3 rwGrid(D_DIM * D_DIM / (256 * 4), 3);
    round_w_kernel<<<rwGrid, 256>>>(wq, wk, wv, p_wr);
    wo_fold_kernel<<<1024 * 512 / 256, 256>>>(wo, gamma, p_wr + (size_t)3 * D_DIM * D_DIM);
    bias2_stage1<<<dim3(D_DIM / 128, 16), 256>>>(wo, beta);
    bias2_stage2<<<D_DIM / 256, 256>>>(bo);

    rope_table_kernel<<<S_LEN * 64 / 256, 256>>>(positions);

    rmsnorm_kernel<<<M, 256>>>(x, g, p_xn);

    cudaFuncSetAttribute(gemm_tf32, cudaFuncAttributeMaxDynamicSharedMemorySize, GEMM_SMEM);
    // QKV projections with fused RoPE on Q,K (z<=1); Q additionally pre-scaled
    dim3 qkvGrid(D_DIM / CTA_N, M / CTA_M, 3);
    gemm_tf32<<<qkvGrid, 256, GEMM_SMEM>>>(p_xn, p_wr, 0, D_DIM, 1, 1,
                                           bq, bk, bv, p_q, p_k, p_v);

    lam_kernel<<<1, 256>>>(lq1, lk1, lq2, lk2, lam_init);

    cudaFuncSetAttribute(flash_wmma, cudaFuncAttributeMaxDynamicSharedMemorySize, FLASH_SMEM);
    dim3 flashGrid(S_LEN / FM, NH, B_SZ);
    flash_wmma<<<flashGrid, 256, FLASH_SMEM>>>(p_q, p_k, p_v, p_attn);

    combine_kernel<<<M, 256>>>(p_attn, p_ctx);

    // O projection with folded weight: K = 1024
    dim3 oGrid(D_DIM / CTA_N, M / CTA_M, 1);
    gemm_tf32<<<oGrid, 256, GEMM_SMEM>>>(p_ctx, p_wr, 3, D_DIM / 2, 0, 0,
                                         p_bias2, p_bias2, p_bias2, out, out, out);
}

// round 17
// speedup vs baseline: 1.0489x; 1.0489x over previous
#include <cuda_runtime.h>
#include <cuda_bf16.h>
#include <math.h>
#include <mma.h>
#include <cstdint>

using namespace nvcuda;

#define B_SZ 2
#define S_LEN 2048
#define D_DIM 2048
#define NH 16
#define HD 128
#define HALF_H 8
#define EPS_RMS 1e-6f
#define EPS_HN 1e-5f
// 1/sqrt(128) * log2(e): folded into Q so QK^T scores are log2-domain
#define QSCALE 0.12751743f

// ---------------- scratch (no allocations allowed) ----------------
__device__ float g_xn[B_SZ * S_LEN * D_DIM];
__device__ float g_q [B_SZ * S_LEN * D_DIM];
__device__ float g_k [B_SZ * S_LEN * D_DIM];
__device__ float g_v [B_SZ * S_LEN * D_DIM];
__device__ float g_attn[B_SZ * S_LEN * D_DIM];
__device__ float g_ctx [B_SZ * S_LEN * (D_DIM / 2)];   // y only: [4096][1024]
__device__ float g_wr  [4 * D_DIM * D_DIM];   // 0-2: wq,wk,wv rounded; 3: wo2 [1024][2048]
__device__ float g_bias2[D_DIM];
__device__ float g_bias_part[16 * D_DIM];
__device__ float g_rope[2 * S_LEN * 64];      // cos | sin tables
__device__ float g_lam[HALF_H];

// ---------------- helpers ----------------
__device__ __forceinline__ uint32_t smem_u32(const void* p) {
    uint32_t a;
    asm("{ .reg .u64 t; cvta.to.shared.u64 t, %1; cvt.u32.u64 %0, t; }" : "=r"(a) : "l"(p));
    return a;
}
__device__ __forceinline__ void cp_async16(uint32_t dst, const void* src) {
    asm volatile("cp.async.cg.shared.global [%0], [%1], 16;" :: "r"(dst), "l"(src));
}
__device__ __forceinline__ void cp_commit() {
    asm volatile("cp.async.commit_group;");
}
template<int N> __device__ __forceinline__ void cp_wait() {
    asm volatile("cp.async.wait_group %0;" :: "n"(N));
}

// ---------------- tf32 rounding of wq,wk,wv ----------------
__global__ __launch_bounds__(256) void round_w_kernel(const float* __restrict__ w0,
                                                      const float* __restrict__ w1,
                                                      const float* __restrict__ w2,
                                                      float* __restrict__ dst) {
    const int z = blockIdx.y;
    const float* src = (z == 0) ? w0 : (z == 1) ? w1 : w2;
    float* d = dst + (size_t)z * D_DIM * D_DIM;
    int i4 = blockIdx.x * 256 + threadIdx.x;
    float4 v = *(const float4*)(src + (size_t)i4 * 4);
    v.x = wmma::__float_to_tf32(v.x); v.y = wmma::__float_to_tf32(v.y);
    v.z = wmma::__float_to_tf32(v.z); v.w = wmma::__float_to_tf32(v.w);
    *(float4*)(d + (size_t)i4 * 4) = v;
}

// ---------------- fold wo ----------------
__global__ __launch_bounds__(256) void wo_fold_kernel(const float* __restrict__ wo,
                                                      const float* __restrict__ gamma,
                                                      float* __restrict__ dst) {
    int i4 = blockIdx.x * 256 + threadIdx.x;      // over 1024*512 float4
    int row = i4 >> 9;                            // 0..1023
    int c4 = i4 & 511;
    int h = row >> 7;
    float g1 = gamma[h], g2 = gamma[h + 8];
    float4 a = *(const float4*)(wo + (size_t)row * D_DIM + c4 * 4);
    float4 b = *(const float4*)(wo + (size_t)(row + 1024) * D_DIM + c4 * 4);
    float4 v;
    v.x = wmma::__float_to_tf32(g1 * a.x + g2 * b.x);
    v.y = wmma::__float_to_tf32(g1 * a.y + g2 * b.y);
    v.z = wmma::__float_to_tf32(g1 * a.z + g2 * b.z);
    v.w = wmma::__float_to_tf32(g1 * a.w + g2 * b.w);
    *(float4*)(dst + (size_t)row * D_DIM + c4 * 4) = v;
}

// ---------------- bias2 = bo + beta_vec @ wo : two-stage reduction ----------------
__global__ __launch_bounds__(256) void bias2_stage1(const float* __restrict__ wo,
                                                    const float* __restrict__ beta) {
    const int nb = blockIdx.x, db = blockIdx.y;
    const int nl = threadIdx.x & 127;
    const int dhalf = threadIdx.x >> 7;
    const int n = nb * 128 + nl;
    float s = 0.f;
#pragma unroll 4
    for (int i = 0; i < 64; i++) {
        int d = db * 128 + dhalf * 64 + i;
        s = fmaf(beta[d >> 7], wo[(size_t)d * D_DIM + n], s);
    }
    __shared__ float sh[256];
    sh[threadIdx.x] = s;
    __syncthreads();
    if (dhalf == 0)
        g_bias_part[db * D_DIM + n] = s + sh[threadIdx.x + 128];
}
__global__ __launch_bounds__(256) void bias2_stage2(const float* __restrict__ bo) {
    int n = blockIdx.x * 256 + threadIdx.x;
    float s = bo[n];
#pragma unroll
    for (int i = 0; i < 16; i++) s += g_bias_part[i * D_DIM + n];
    g_bias2[n] = s;
}

// ---------------- RMSNorm, float4 (emits tf32-rounded output) ----------------
__global__ __launch_bounds__(256) void rmsnorm_kernel(const float* __restrict__ x,
                                                      const float* __restrict__ g,
                                                      float* __restrict__ out) {
    int row = blockIdx.x;
    const float* xr = x + (size_t)row * D_DIM;
    float* orow = out + (size_t)row * D_DIM;
    float4 xv[2];
    float s = 0.f;
#pragma unroll
    for (int it = 0; it < 2; it++) {
        xv[it] = *(const float4*)(xr + (threadIdx.x + it * 256) * 4);
        float a0 = xv[it].x + 2.f * EPS_RMS, a1 = xv[it].y + 2.f * EPS_RMS;
        float a2 = xv[it].z + 2.f * EPS_RMS, a3 = xv[it].w + 2.f * EPS_RMS;
        s = fmaf(a0, a0, s); s = fmaf(a1, a1, s);
        s = fmaf(a2, a2, s); s = fmaf(a3, a3, s);
    }
#pragma unroll
    for (int off = 16; off; off >>= 1) s += __shfl_xor_sync(0xffffffffu, s, off);
    __shared__ float red[8];
    __shared__ float sinv;
    if ((threadIdx.x & 31) == 0) red[threadIdx.x >> 5] = s;
    __syncthreads();
    if (threadIdx.x == 0) {
        float t = 0.f;
#pragma unroll
        for (int i = 0; i < 8; i++) t += red[i];
        float n = sqrtf(t) * 45.254833995939045f;  // sqrt(2048)
        sinv = 1.0f / (n + EPS_RMS);
    }
    __syncthreads();
    float inv = sinv;
#pragma unroll
    for (int it = 0; it < 2; it++) {
        int d = (threadIdx.x + it * 256) * 4;
        float4 gv = *(const float4*)(g + d);
        float4 o;
        o.x = wmma::__float_to_tf32((xv[it].x + EPS_RMS) * inv * gv.x);
        o.y = wmma::__float_to_tf32((xv[it].y + EPS_RMS) * inv * gv.y);
        o.z = wmma::__float_to_tf32((xv[it].z + EPS_RMS) * inv * gv.z);
        o.w = wmma::__float_to_tf32((xv[it].w + EPS_RMS) * inv * gv.w);
        *(float4*)(orow + d) = o;
    }
}

// ---------------- TF32 WMMA GEMM, cp.async 3-stage GBK=32 (proven config) ----------------
#define CTA_M 128
#define CTA_N 256
#define GBK 32
#define LDA 36
#define LDB 260
#define LDC 132
#define STAGE_A (CTA_M * LDA)
#define STAGE_B (GBK * LDB)
#define STAGE_FL (STAGE_A + STAGE_B)
#define NSTAGE 3
#define GEMM_SMEM (NSTAGE * STAGE_FL * 4)

__global__ __launch_bounds__(256) void gemm_tf32(const float* __restrict__ A,
                                                 const float* __restrict__ Wbase,
                                                 int zoff, int Kdim, int roundOut, int doRope,
                                                 const float* __restrict__ b0,
                                                 const float* __restrict__ b1,
                                                 const float* __restrict__ b2,
                                                 float* __restrict__ C0,
                                                 float* __restrict__ C1,
                                                 float* __restrict__ C2) {
    extern __shared__ float sm[];
    const uint32_t smem_base = smem_u32(sm);
    const int z = blockIdx.z;
    const float* W    = Wbase + (size_t)(z + zoff) * D_DIM * D_DIM;
    const float* bias = (z == 0) ? b0 : (z == 1) ? b1 : b2;
    float* C          = (z == 0) ? C0 : (z == 1) ? C1 : C2;

    const int tid = threadIdx.x;
    const int warpId = tid >> 5;
    const int wy = warpId >> 2;
    const int wx = warpId & 3;
    const int mBase = blockIdx.y * CTA_M;
    const int nBase = blockIdx.x * CTA_N;
    const int nkt = Kdim / GBK;
    const bool rope = doRope && (z <= 1);
    const float qs = (z == 0) ? QSCALE : 1.0f;

    wmma::fragment<wmma::accumulator, 16, 16, 8, float> acc[4][4];
#pragma unroll
    for (int i = 0; i < 4; i++)
#pragma unroll
        for (int j = 0; j < 4; j++) wmma::fill_fragment(acc[i][j], 0.0f);

    auto stage = [&](int buf, int k0) {
        uint32_t sa = smem_base + (uint32_t)(buf * STAGE_FL * 4);
        uint32_t sb = sa + STAGE_A * 4;
#pragma unroll
        for (int it = 0; it < 4; it++) {
            int idx = tid + it * 256;
            int row = idx >> 3, c = idx & 7;
            cp_async16(sa + (uint32_t)(row * LDA + c * 4) * 4,
                       A + (size_t)(mBase + row) * Kdim + k0 + c * 4);
        }
#pragma unroll
        for (int it = 0; it < 8; it++) {
            int idx = tid + it * 256;
            int row = idx >> 6, c = idx & 63;
            cp_async16(sb + (uint32_t)(row * LDB + c * 4) * 4,
                       W + (size_t)(k0 + row) * D_DIM + nBase + c * 4);
        }
    };

    stage(0, 0);        cp_commit();
    stage(1, GBK);      cp_commit();

    for (int t = 0; t < nkt; t++) {
        const int buf = t % 3;
        if (t + 1 < nkt) cp_wait<1>(); else cp_wait<0>();
        __syncthreads();

        const float* As = sm + buf * STAGE_FL;
        const float* Bs = As + STAGE_A;
#pragma unroll
        for (int kk = 0; kk < GBK; kk += 8) {
            wmma::fragment<wmma::matrix_a, 16, 16, 8, wmma::precision::tf32, wmma::row_major> af[4];
            wmma::fragment<wmma::matrix_b, 16, 16, 8, wmma::precision::tf32, wmma::row_major> bf[4];
#pragma unroll
            for (int i = 0; i < 4; i++)
                wmma::load_matrix_sync(af[i], &As[(wy * 64 + i * 16) * LDA + kk], LDA);
#pragma unroll
            for (int j = 0; j < 4; j++)
                wmma::load_matrix_sync(bf[j], &Bs[kk * LDB + wx * 64 + j * 16], LDB);
#pragma unroll
            for (int i = 0; i < 4; i++)
#pragma unroll
                for (int j = 0; j < 4; j++)
                    wmma::mma_sync(acc[i][j], af[i], bf[j], acc[i][j]);
        }

        if (t + 2 < nkt) { stage((t + 2) % 3, (t + 2) * GBK); cp_commit(); }
    }
    __syncthreads();

    float* Cs = sm;
#pragma unroll
    for (int half = 0; half < 2; half++) {
        if ((wx >> 1) == half) {
#pragma unroll
            for (int i = 0; i < 4; i++)
#pragma unroll
                for (int j = 0; j < 4; j++)
                    wmma::store_matrix_sync(&Cs[(wy * 64 + i * 16) * LDC + (wx & 1) * 64 + j * 16],
                                            acc[i][j], LDC, wmma::mem_row_major);
        }
        __syncthreads();
        if (rope) {
#pragma unroll
            for (int it = 0; it < 8; it++) {
                int idx = tid + it * 256;          // 2048 = 128 rows x 16 f4 (cols 0..63)
                int row = idx >> 4, c4 = idx & 15;
                int j = c4 * 4;
                float4 a = *(float4*)&Cs[row * LDC + j];
                float4 b = *(float4*)&Cs[row * LDC + j + 64];
                int col = nBase + half * 128 + j;
                float4 bi  = *(const float4*)(bias + col);
                float4 bi2 = *(const float4*)(bias + col + 64);
                a.x = (a.x + bi.x) * qs;  a.y = (a.y + bi.y) * qs;
                a.z = (a.z + bi.z) * qs;  a.w = (a.w + bi.w) * qs;
                b.x = (b.x + bi2.x) * qs; b.y = (b.y + bi2.y) * qs;
                b.z = (b.z + bi2.z) * qs; b.w = (b.w + bi2.w) * qs;
                int s = (mBase + row) & (S_LEN - 1);
                float4 co = *(const float4*)&g_rope[s * 64 + j];
                float4 si = *(const float4*)&g_rope[S_LEN * 64 + s * 64 + j];
                float4 lo, hi;
                lo.x = wmma::__float_to_tf32(a.x * co.x - b.x * si.x);
                lo.y = wmma::__float_to_tf32(a.y * co.y - b.y * si.y);
                lo.z = wmma::__float_to_tf32(a.z * co.z - b.z * si.z);
                lo.w = wmma::__float_to_tf32(a.w * co.w - b.w * si.w);
                hi.x = wmma::__float_to_tf32(b.x * co.x + a.x * si.x);
                hi.y = wmma::__float_to_tf32(b.y * co.y + a.y * si.y);
                hi.z = wmma::__float_to_tf32(b.z * co.z + a.z * si.z);
                hi.w = wmma::__float_to_tf32(b.w * co.w + a.w * si.w);
                float* Crow = C + (size_t)(mBase + row) * D_DIM + col;
                *(float4*)Crow = lo;
                *(float4*)(Crow + 64) = hi;
            }
        } else {
#pragma unroll
            for (int it = 0; it < 16; it++) {
                int idx = tid + it * 256;
                int row = idx >> 5, c = idx & 31;
                float4 v = *(float4*)&Cs[row * LDC + c * 4];
                int col = nBase + half * 128 + c * 4;
                float4 bi = *(const float4*)(bias + col);
                v.x += bi.x; v.y += bi.y; v.z += bi.z; v.w += bi.w;
                if (roundOut) {
                    v.x = wmma::__float_to_tf32(v.x); v.y = wmma::__float_to_tf32(v.y);
                    v.z = wmma::__float_to_tf32(v.z); v.w = wmma::__float_to_tf32(v.w);
                }
                *(float4*)(C + (size_t)(mBase + row) * D_DIM + col) = v;
            }
        }
        __syncthreads();
    }
}

// ---------------- RoPE table (fp64, once) ----------------
__global__ __launch_bounds__(256) void rope_table_kernel(const int* __restrict__ positions) {
    int idx = blockIdx.x * 256 + threadIdx.x;      // S_LEN*64
    int j = idx & 63;
    int s = idx >> 6;
    double e = (double)(2 * j) * (1.0 / 128.0);
    double invf = exp(-e * 13.122363377404328);    // ln(500000)
    double f = (double)positions[s] * invf;
    g_rope[idx] = (float)cos(f);
    g_rope[S_LEN * 64 + idx] = (float)sin(f);
}

// ---------------- lambda per head ----------------
__global__ __launch_bounds__(256) void lam_kernel(const float* __restrict__ lq1,
                                                  const float* __restrict__ lk1,
                                                  const float* __restrict__ lq2,
                                                  const float* __restrict__ lk2,
                                                  const float* __restrict__ lam_init) {
    int h = threadIdx.x >> 5;
    int lane = threadIdx.x & 31;
    float s1 = 0.f, s2 = 0.f;
#pragma unroll
    for (int d = lane; d < HD; d += 32) {
        s1 = fmaf(lq1[h * HD + d], lk1[h * HD + d], s1);
        s2 = fmaf(lq2[h * HD + d], lk2[h * HD + d], s2);
    }
#pragma unroll
    for (int off = 16; off; off >>= 1) {
        s1 += __shfl_xor_sync(0xffffffffu, s1, off);
        s2 += __shfl_xor_sync(0xffffffffu, s2, off);
    }
    if (lane == 0 && h < HALF_H) {
        float l = expf(s1) - expf(s2) + lam_init[h];
        g_lam[h] = fminf(fmaxf(l, 0.f), 1.f);
    }
}

// ---------------- WMMA flash attention v4: log2 softmax, graded cp.async waits ----------------
#define FM 128
#define FN 64
#define FLDQ 132
#define FLDP 72
#define KV_FL (64 * FLDQ)
#define F_QS 0
#define F_PS (FM * FLDQ)
#define F_B0 (F_PS + FM * FLDP)
#define F_ROW (F_B0 + 3 * KV_FL)
#define F_MI (F_ROW + 256)
#define F_LI (F_MI + FM)
#define F_AL (F_LI + FM)
#define FLASH_SMEM ((F_AL + FM) * 4)      // 208384 B

__global__ __launch_bounds__(256) void flash_wmma(const float* __restrict__ Q,
                                                  const float* __restrict__ K,
                                                  const float* __restrict__ V,
                                                  float* __restrict__ O) {
    extern __shared__ float sm[];
    const uint32_t smem_base = smem_u32(sm);
    float* Qs = sm + F_QS;
    float* Ps = sm + F_PS;
    float* rowtile = sm + F_ROW;
    float* mi = sm + F_MI;
    float* li = sm + F_LI;
    float* al = sm + F_AL;

    const int qBase = (gridDim.x - 1 - blockIdx.x) * FM;   // heavy blocks first
    const int h = blockIdx.y;
    const int b = blockIdx.z;
    const int tid = threadIdx.x;
    const int warp = tid >> 5;
    const int wy = warp >> 1;
    const int wx = warp & 1;
    const size_t headOff = (size_t)h * HD;
    const int nIter = qBase / FN + 2;

    auto stageTile = [&](int fOff, const float* src, int n0) {
#pragma unroll
        for (int it = 0; it < 8; it++) {
            int idx = tid + it * 256;
            int row = idx >> 5, c4 = idx & 31;
            cp_async16(smem_base + (uint32_t)(fOff + row * FLDQ + c4 * 4) * 4,
                       src + ((size_t)(b * S_LEN + n0 + row)) * D_DIM + headOff + c4 * 4);
        }
    };

#pragma unroll
    for (int it = 0; it < 16; it++) {
        int idx = tid + it * 256;
        int row = idx >> 5, c4 = idx & 31;
        cp_async16(smem_base + (uint32_t)(F_QS + row * FLDQ + c4 * 4) * 4,
                   Q + ((size_t)(b * S_LEN + qBase + row)) * D_DIM + headOff + c4 * 4);
    }
    stageTile(F_B0, K, 0);
    stageTile(F_B0 + KV_FL, V, 0);
    cp_commit();

    rowtile[tid] = (float)(tid >> 4);
    if (tid < FM) { mi[tid] = -1e30f; li[tid] = 0.f; }
    cp_wait<0>();
    __syncthreads();

    wmma::fragment<wmma::accumulator, 16, 16, 8, float> rf;
    wmma::load_matrix_sync(rf, rowtile, 16, wmma::mem_row_major);

    wmma::fragment<wmma::accumulator, 16, 16, 8, float> oacc[2][4];
#pragma unroll
    for (int i = 0; i < 2; i++)
#pragma unroll
        for (int j = 0; j < 4; j++) wmma::fill_fragment(oacc[i][j], 0.f);

    for (int t = 0; t < nIter; t++) {
        const int kb = (3 - (t % 3)) % 3;
        const int vb = (kb + 1) % 3;
        const int fb = 3 - kb - vb;
        float* Ks = sm + F_B0 + kb * KV_FL;
        float* Vs = sm + F_B0 + vb * KV_FL;
        const int n0 = t * FN;
        const bool more = (t + 1 < nIter);

        if (more) { stageTile(F_B0 + fb * KV_FL, K, n0 + FN); cp_commit(); }

        // ---- S = Q @ K^T (Q pre-scaled: log2-domain scores)
        {
            const int sx = warp & 1;
            wmma::fragment<wmma::accumulator, 16, 16, 8, float> sacc[2][2];
#pragma unroll
            for (int i = 0; i < 2; i++)
#pragma unroll
                for (int j = 0; j < 2; j++) wmma::fill_fragment(sacc[i][j], 0.f);
#pragma unroll
            for (int k = 0; k < HD; k += 8) {
                wmma::fragment<wmma::matrix_a, 16, 16, 8, wmma::precision::tf32, wmma::row_major> af[2];
                wmma::fragment<wmma::matrix_b, 16, 16, 8, wmma::precision::tf32, wmma::col_major> bf[2];
#pragma unroll
                for (int i = 0; i < 2; i++)
                    wmma::load_matrix_sync(af[i], &Qs[(wy * 32 + i * 16) * FLDQ + k], FLDQ);
#pragma unroll
                for (int j = 0; j < 2; j++)
                    wmma::load_matrix_sync(bf[j], &Ks[(sx * 32 + j * 16) * FLDQ + k], FLDQ);
#pragma unroll
                for (int i = 0; i < 2; i++)
#pragma unroll
                    for (int j = 0; j < 2; j++)
                        wmma::mma_sync(sacc[i][j], af[i], bf[j], sacc[i][j]);
            }
#pragma unroll
            for (int i = 0; i < 2; i++)
#pragma unroll
                for (int j = 0; j < 2; j++)
                    wmma::store_matrix_sync(&Ps[(wy * 32 + i * 16) * FLDP + sx * 32 + j * 16],
                                            sacc[i][j], FLDP, wmma::mem_row_major);
        }
        __syncthreads();

        if (more) { stageTile(F_B0 + kb * KV_FL, V, n0 + FN); cp_commit(); }

        // ---- online softmax (log2 domain): registers, masked only on last 2 tiles
        {
            int r = tid >> 1;
            int part = tid & 1;
            float* Prow = Ps + r * FLDP + part * 32;
            float v[32];
            float lm = -1e30f;
            if (t >= nIter - 2) {
                int cbase = n0 + part * 32 - qBase - r;
#pragma unroll
                for (int n = 0; n < 32; n++) {
                    float x = Prow[n];
                    if (cbase + n > 0) x = -1e30f;
                    v[n] = x;
                    lm = fmaxf(lm, x);
                }
            } else {
#pragma unroll
                for (int n = 0; n < 32; n++) {
                    v[n] = Prow[n];
                    lm = fmaxf(lm, v[n]);
                }
            }
            lm = fmaxf(lm, __shfl_xor_sync(0xffffffffu, lm, 1));
            float oldm = mi[r];
            float newm = fmaxf(oldm, lm);
            float lsum = 0.f;
#pragma unroll
            for (int n = 0; n < 32; n++) {
                float e = exp2f(v[n] - newm);
                Prow[n] = wmma::__float_to_tf32(e);
                lsum += e;
            }
            lsum += __shfl_xor_sync(0xffffffffu, lsum, 1);
            if (part == 0) {
                float alpha = exp2f(oldm - newm);
                mi[r] = newm;
                li[r] = li[r] * alpha + lsum;
                al[r] = alpha;
            }
        }
        // graded wait: retire V(t); K(t+1)/V(t+1) may remain in flight
        if (more) cp_wait<2>(); else cp_wait<0>();
        __syncthreads();

        // ---- rescale O accumulators (rowid trick)
#pragma unroll
        for (int e = 0; e < 8; e++) {
            int rl = (int)rf.x[e];
            float a0 = al[wy * 32 + rl];
            float a1 = al[wy * 32 + 16 + rl];
#pragma unroll
            for (int j = 0; j < 4; j++) {
                oacc[0][j].x[e] *= a0;
                oacc[1][j].x[e] *= a1;
            }
        }

        // ---- O += P @ V
#pragma unroll
        for (int k = 0; k < FN; k += 8) {
            wmma::fragment<wmma::matrix_a, 16, 16, 8, wmma::precision::tf32, wmma::row_major> af[2];
            wmma::fragment<wmma::matrix_b, 16, 16, 8, wmma::precision::tf32, wmma::row_major> bf[4];
#pragma unroll
            for (int i = 0; i < 2; i++)
                wmma::load_matrix_sync(af[i], &Ps[(wy * 32 + i * 16) * FLDP + k], FLDP);
#pragma unroll
            for (int j = 0; j < 4; j++)
                wmma::load_matrix_sync(bf[j], &Vs[k * FLDQ + wx * 64 + j * 16], FLDQ);
#pragma unroll
            for (int i = 0; i < 2; i++)
#pragma unroll
                for (int j = 0; j < 4; j++)
                    wmma::mma_sync(oacc[i][j], af[i], bf[j], oacc[i][j]);
        }

        // retire K(t+1) before next S-phase; V(t+1) stays outstanding
        if (more) cp_wait<1>();
        __syncthreads();
    }

    // epilogue: normalize in registers, store fragments directly to global
#pragma unroll
    for (int e = 0; e < 8; e++) {
        int rl = (int)rf.x[e];
        float i0 = 1.0f / li[wy * 32 + rl];
        float i1 = 1.0f / li[wy * 32 + 16 + rl];
#pragma unroll
        for (int j = 0; j < 4; j++) {
            oacc[0][j].x[e] *= i0;
            oacc[1][j].x[e] *= i1;
        }
    }
#pragma unroll
    for (int i = 0; i < 2; i++)
#pragma unroll
        for (int j = 0; j < 4; j++)
            wmma::store_matrix_sync(
                O + ((size_t)(b * S_LEN + qBase + wy * 32 + i * 16)) * D_DIM + headOff + wx * 64 + j * 16,
                oacc[i][j], D_DIM, wmma::mem_row_major);
}

// ---------------- diff combine + headwise LayerNorm (warp per row x head, float4) ----------------
__global__ __launch_bounds__(256) void combine_kernel(const float* __restrict__ attn,
                                                      float* __restrict__ ctx) {
    int row = blockIdx.x;                 // 0..4095
    int h = threadIdx.x >> 5;             // 0..7
    int lane = threadIdx.x & 31;
    size_t base = (size_t)row * D_DIM;
    float lam = g_lam[h];

    float4 a1 = *(const float4*)(attn + base + h * HD + lane * 4);
    float4 a2 = *(const float4*)(attn + base + (h + 8) * HD + lane * 4);
    float4 o;
    o.x = a1.x - lam * a2.x; o.y = a1.y - lam * a2.y;
    o.z = a1.z - lam * a2.z; o.w = a1.w - lam * a2.w;

    float s = o.x + o.y + o.z + o.w;
#pragma unroll
    for (int off = 16; off; off >>= 1) s += __shfl_xor_sync(0xffffffffu, s, off);
    float mean = s * (1.0f / 128.0f);

    float dx = o.x - mean, dy = o.y - mean, dz = o.z - mean, dw = o.w - mean;
    float s2 = dx * dx + dy * dy + dz * dz + dw * dw;
#pragma unroll
    for (int off = 16; off; off >>= 1) s2 += __shfl_xor_sync(0xffffffffu, s2, off);
    float inv = rsqrtf(s2 * (1.0f / 128.0f) + EPS_HN);

    float4 y;
    y.x = wmma::__float_to_tf32(dx * inv);
    y.y = wmma::__float_to_tf32(dy * inv);
    y.z = wmma::__float_to_tf32(dz * inv);
    y.w = wmma::__float_to_tf32(dw * inv);
    *(float4*)(ctx + (size_t)row * (D_DIM / 2) + h * HD + lane * 4) = y;
}

// ---------------- launch ----------------
extern "C" void kernel_launch(void* const* d_in, const int* in_sizes, int n_in,
                              void* d_out, int out_size) {
    const float* x         = (const float*)d_in[0];
    const int*   positions = (const int*)  d_in[1];
    const float* wq        = (const float*)d_in[2];
    const float* bq        = (const float*)d_in[3];
    const float* wk        = (const float*)d_in[4];
    const float* bk        = (const float*)d_in[5];
    const float* wv        = (const float*)d_in[6];
    const float* bv        = (const float*)d_in[7];
    const float* wo        = (const float*)d_in[8];
    const float* bo        = (const float*)d_in[9];
    const float* g         = (const float*)d_in[10];
    const float* gamma     = (const float*)d_in[11];
    const float* beta      = (const float*)d_in[12];
    const float* lam_init  = (const float*)d_in[13];
    const float* lq1       = (const float*)d_in[14];
    const float* lk1       = (const float*)d_in[15];
    const float* lq2       = (const float*)d_in[16];
    const float* lk2       = (const float*)d_in[17];
    float* out = (float*)d_out;

    float *p_xn, *p_q, *p_k, *p_v, *p_attn, *p_ctx, *p_wr, *p_bias2;
    cudaGetSymbolAddress((void**)&p_xn,   g_xn);
    cudaGetSymbolAddress((void**)&p_q,    g_q);
    cudaGetSymbolAddress((void**)&p_k,    g_k);
    cudaGetSymbolAddress((void**)&p_v,    g_v);
    cudaGetSymbolAddress((void**)&p_attn, g_attn);
    cudaGetSymbolAddress((void**)&p_ctx,  g_ctx);
    cudaGetSymbolAddress((void**)&p_wr,   g_wr);
    cudaGetSymbolAddress((void**)&p_bias2, g_bias2);

    const int M = B_SZ * S_LEN;   // 4096

    dim3 rwGrid(D_DIM * D_DIM / (256 * 4), 3);
    round_w_kernel<<<rwGrid, 256>>>(wq, wk, wv, p_wr);
    wo_fold_kernel<<<1024 * 512 / 256, 256>>>(wo, gamma, p_wr + (size_t)3 * D_DIM * D_DIM);
    bias2_stage1<<<dim3(D_DIM / 128, 16), 256>>>(wo, beta);
    bias2_stage2<<<D_DIM / 256, 256>>>(bo);

    rope_table_kernel<<<S_LEN * 64 / 256, 256>>>(positions);

    rmsnorm_kernel<<<M, 256>>>(x, g, p_xn);

    cudaFuncSetAttribute(gemm_tf32, cudaFuncAttributeMaxDynamicSharedMemorySize, GEMM_SMEM);
    // QKV projections with fused RoPE on Q,K (z<=1); Q additionally pre-scaled
    dim3 qkvGrid(D_DIM / CTA_N, M / CTA_M, 3);
    gemm_tf32<<<qkvGrid, 256, GEMM_SMEM>>>(p_xn, p_wr, 0, D_DIM, 1, 1,
                                           bq, bk, bv, p_q, p_k, p_v);

    lam_kernel<<<1, 256>>>(lq1, lk1, lq2, lk2, lam_init);

    cudaFuncSetAttribute(flash_wmma, cudaFuncAttributeMaxDynamicSharedMemorySize, FLASH_SMEM);
    dim3 flashGrid(S_LEN / FM, NH, B_SZ);
    flash_wmma<<<flashGrid, 256, FLASH_SMEM>>>(p_q, p_k, p_v, p_attn);

    combine_kernel<<<M, 256>>>(p_attn, p_ctx);

    // O projection with folded weight: K = 1024
    dim3 oGrid(D_DIM / CTA_N, M / CTA_M, 1);
    gemm_tf32<<<oGrid, 256, GEMM_SMEM>>>(p_ctx, p_wr, 3, D_DIM / 2, 0, 0,
                                         p_bias2, p_bias2, p_bias2, out, out, out);
}